// round 13
// baseline (speedup 1.0000x reference)
#include <cuda_runtime.h>
#include <math_constants.h>

#define BB   2
#define NN   32768
#define NCC  1024
#define SS   32
#define MM   (NCC*SS)          // 32768

#define NN_WARPS  8
#define GQ        8                 // queries per warp (grouped)
#define QPB       (NN_WARPS*GQ)    // 64 queries per block

#define P2C_PT    2                 // points per thread in k_p2c
#define QP_PT     4                 // queries per thread in k_qprep

// Scratch (no allocations allowed) ------------------------------------------
__device__ float4       g_xyzp [BB*NN];
__device__ float4       g_ctr  [BB*NCC];
__device__ float        g_csx [BB*NCC], g_csy[BB*NCC], g_csz[BB*NCC];
__device__ float4       g_cen [BB*NCC];   // member centroid (x,y,z,|cen|^2)
__device__ int          g_assign[BB*NN];
__device__ int          g_cnt [BB*NCC];
__device__ int          g_start[BB*NCC];
__device__ int          g_cur [BB*NCC];
__device__ unsigned int g_rmax2[BB*NCC];  // max member->centroid distance (bits)
__device__ float4       g_psort[BB*NN];
__device__ int          g_qseed[BB*MM];
__device__ int          g_qcnt [BB*NCC];
__device__ int          g_qcur [BB*NCC];
__device__ unsigned     g_qkey [BB*MM];   // (cid<<16) | q_local
__device__ float4       g_qpt  [BB*MM];
__device__ float        g_mind[BB*MM];
__device__ float        g_acc[4];
__device__ int          g_done;

// ---------------------------------------------------------------------------
__device__ __forceinline__ float warpMin(float v) {
    #pragma unroll
    for (int o = 16; o > 0; o >>= 1)
        v = fminf(v, __shfl_xor_sync(0xffffffffu, v, o));
    return v;
}

__inline__ __device__ float blockReduceSum(float v) {
    __shared__ float sw[32];
    #pragma unroll
    for (int o = 16; o > 0; o >>= 1) v += __shfl_down_sync(0xffffffffu, v, o);
    int lane = threadIdx.x & 31, w = threadIdx.x >> 5;
    if (lane == 0) sw[w] = v;
    __syncthreads();
    int nw = blockDim.x >> 5;
    v = (threadIdx.x < nw) ? sw[threadIdx.x] : 0.0f;
    if (w == 0) {
        #pragma unroll
        for (int o = 16; o > 0; o >>= 1) v += __shfl_down_sync(0xffffffffu, v, o);
    }
    return v;
}

// Init: pack centers, zero counters ------------------------------------------
__global__ void k_prep(const float* __restrict__ ctr) {
    int i = blockIdx.x * blockDim.x + threadIdx.x;   // 0..BB*NCC-1
    float x = ctr[3*i+0], y = ctr[3*i+1], z = ctr[3*i+2];
    g_ctr[i] = make_float4(x, y, z, x*x + y*y + z*z);
    g_cnt[i] = 0;
    g_qcnt[i] = 0;
    g_rmax2[i] = 0u;
    g_csx[i] = 0.f; g_csy[i] = 0.f; g_csz[i] = 0.f;
    if (i < 4) g_acc[i] = 0.0f;
    if (i == 4) g_done = 0;
}

// Part 1: xyz -> nearest center. 2 points/thread share each center LDS. -------
__global__ void k_p2c(const float* __restrict__ xyz, const float* __restrict__ radius) {
    __shared__ float4 shc[NCC];
    const int b = blockIdx.y;
    const int n0 = (blockIdx.x * blockDim.x + threadIdx.x) * P2C_PT;
    for (int i = threadIdx.x; i < NCC; i += blockDim.x)
        shc[i] = g_ctr[b*NCC + i];
    __syncthreads();

    float ax[P2C_PT], ay[P2C_PT], az[P2C_PT], qw[P2C_PT], tmin[P2C_PT];
    int idx[P2C_PT];
    #pragma unroll
    for (int j = 0; j < P2C_PT; ++j) {
        const float* pp = xyz + ((long long)b*NN + n0 + j) * 3;
        float x = pp[0], y = pp[1], z = pp[2];
        qw[j] = x*x + y*y + z*z;
        g_xyzp[b*NN + n0 + j] = make_float4(x, y, z, qw[j]);
        ax[j] = -2.0f*x; ay[j] = -2.0f*y; az[j] = -2.0f*z;
        tmin[j] = CUDART_INF_F; idx[j] = 0;
    }
    #pragma unroll 4
    for (int c = 0; c < NCC; ++c) {
        float4 p = shc[c];
        #pragma unroll
        for (int j = 0; j < P2C_PT; ++j) {
            float t = fmaf(ax[j], p.x, p.w);
            t = fmaf(ay[j], p.y, t);
            t = fmaf(az[j], p.z, t);
            if (t < tmin[j]) { tmin[j] = t; idx[j] = c; }  // strict < == jnp.argmin
        }
    }
    float contrib = 0.0f;
    #pragma unroll
    for (int j = 0; j < P2C_PT; ++j) {
        float cd = sqrtf(fmaxf(tmin[j] + qw[j], 1e-12f));
        contrib += fmaxf(cd - radius[b*NCC + idx[j]], 0.0f);
        int bc = b*NCC + idx[j];
        g_assign[b*NN + n0 + j] = idx[j];
        atomicAdd(&g_cnt[bc], 1);
        float4 pt = g_xyzp[b*NN + n0 + j];
        atomicAdd(&g_csx[bc], pt.x);
        atomicAdd(&g_csy[bc], pt.y);
        atomicAdd(&g_csz[bc], pt.z);
    }
    float s = blockReduceSum(contrib);
    if (threadIdx.x == 0) atomicAdd(&g_acc[b], s);
}

// Query prepass: 4 queries/thread share each center LDS ------------------------
__global__ void k_qprep(const float* __restrict__ sp) {
    __shared__ float4 shc[NCC];
    const int b = blockIdx.y;
    const int m0 = (blockIdx.x * blockDim.x + threadIdx.x) * QP_PT;
    for (int i = threadIdx.x; i < NCC; i += blockDim.x) {
        float4 c = g_ctr[b*NCC + i];
        if (g_cnt[b*NCC + i] == 0) c.w = CUDART_INF_F;
        shc[i] = c;
    }
    __syncthreads();

    float ax[QP_PT], ay[QP_PT], az[QP_PT], tmin[QP_PT];
    int idx[QP_PT];
    #pragma unroll
    for (int j = 0; j < QP_PT; ++j) {
        const float* p = sp + ((long long)b*MM + m0 + j) * 3;
        float x = p[0], y = p[1], z = p[2];
        ax[j] = -2.0f*x; ay[j] = -2.0f*y; az[j] = -2.0f*z;
        tmin[j] = CUDART_INF_F; idx[j] = 0;
    }
    #pragma unroll 4
    for (int c = 0; c < NCC; ++c) {
        float4 cc = shc[c];
        #pragma unroll
        for (int j = 0; j < QP_PT; ++j) {
            float t = fmaf(ax[j], cc.x, cc.w);
            t = fmaf(ay[j], cc.y, t);
            t = fmaf(az[j], cc.z, t);
            if (t < tmin[j]) { tmin[j] = t; idx[j] = c; }
        }
    }
    #pragma unroll
    for (int j = 0; j < QP_PT; ++j) {
        g_qseed[b*MM + m0 + j] = idx[j];
        atomicAdd(&g_qcnt[b*NCC + idx[j]], 1);
    }
}

// Warp-shuffle prefix scans + centroid computation ------------------------------
__device__ __forceinline__ void scanHalf(const int* __restrict__ cnt,
                                         int* out0, int* out1, bool dual,
                                         int* wsum) {
    const int t = threadIdx.x, lane = t & 31, w = t >> 5;
    int c0 = cnt[2*t], c1 = cnt[2*t+1];
    int v = c0 + c1, s = v;
    #pragma unroll
    for (int o = 1; o < 32; o <<= 1) {
        int n = __shfl_up_sync(0xffffffffu, s, o);
        if (lane >= o) s += n;
    }
    if (lane == 31) wsum[w] = s;
    __syncthreads();
    if (w == 0) {
        int x = wsum[lane];
        #pragma unroll
        for (int o = 1; o < 32; o <<= 1) {
            int n = __shfl_up_sync(0xffffffffu, x, o);
            if (lane >= o) x += n;
        }
        wsum[lane] = x;
    }
    __syncthreads();
    int base = (w > 0) ? wsum[w-1] : 0;
    int excl = base + s - v;
    out0[2*t]   = excl;  out0[2*t+1] = excl + c0;
    if (dual) { out1[2*t] = excl; out1[2*t+1] = excl + c0; }
    __syncthreads();
}

__global__ void k_scan() {
    __shared__ int wsum[32];
    scanHalf(g_cnt,  g_start, g_cur, true,  wsum);
    scanHalf(g_qcnt, g_qcur,  0,     false, wsum);
    const int t = threadIdx.x;
    #pragma unroll
    for (int j = 0; j < 2; ++j) {
        int i = 2*t + j;
        int c = g_cnt[i];
        float inv = (c > 0) ? 1.0f/(float)c : 0.0f;
        float cx = g_csx[i]*inv, cy = g_csy[i]*inv, cz = g_csz[i]*inv;
        g_cen[i] = make_float4(cx, cy, cz, cx*cx + cy*cy + cz*cz);
    }
}

// Merged scatter + centroid covering radius ------------------------------------
__global__ void k_scatter(const float* __restrict__ sp) {
    int i = blockIdx.x * blockDim.x + threadIdx.x;   // 0..BB*NN-1 (== BB*MM-1)
    if (i >= BB*NN) return;
    int b = i / NN;
    int bc = b*NCC + g_assign[i];
    int pos = atomicAdd(&g_cur[bc], 1);
    float4 pt = g_xyzp[i];
    g_psort[pos] = pt;
    float4 cen = g_cen[bc];
    float dx = pt.x - cen.x, dy = pt.y - cen.y, dz = pt.z - cen.z;
    float rd = sqrtf(dx*dx + dy*dy + dz*dz);
    atomicMax(&g_rmax2[bc], __float_as_uint(rd));    // rd >= 0

    int m = i - b*MM;                                 // NN == MM
    int cid = g_qseed[i];
    int qpos = atomicAdd(&g_qcur[b*NCC + cid], 1);
    const float* p = sp + (long long)i * 3;
    float x = p[0], y = p[1], z = p[2];
    g_qkey[qpos] = ((unsigned)cid << 16) | (unsigned)m;
    g_qpt[qpos]  = make_float4(x, y, z, x*x + y*y + z*z);
}

// Part 2: exact NN, 8 sorted queries per warp; centroid-anchored pruning -------
__global__ void __launch_bounds__(32*NN_WARPS)
k_nn() {
    __shared__ float4 shc[NCC];    // member centroids; w=+inf if empty
    __shared__ int2   shcs[NCC];   // (start, count)
    __shared__ float  shr[NCC];    // padded centroid covering radius
    __shared__ unsigned short shlist[NN_WARPS][NCC];
    const int tid  = threadIdx.x;
    const int lane = tid & 31;
    const int warp = tid >> 5;
    const int qbase = blockIdx.x * QPB + warp * GQ;
    const int b = (blockIdx.x * QPB) / MM;

    for (int i = tid; i < NCC; i += 32*NN_WARPS) {
        int cnt = g_cnt[b*NCC + i];
        float4 c = g_cen[b*NCC + i];
        if (cnt == 0) c.w = CUDART_INF_F;
        shc[i]  = c;
        shcs[i] = make_int2(g_start[b*NCC + i], cnt);
        shr[i]  = __uint_as_float(g_rmax2[b*NCC + i]) * 1.000002f + 1e-6f;
    }
    __syncthreads();

    const float4* __restrict__ pts = g_psort;
    unsigned short* const mylist = shlist[warp];

    float ax[GQ], ay[GQ], az[GQ], qw[GQ], lmin[GQ];
    int   seed[GQ];
    #pragma unroll
    for (int q = 0; q < GQ; ++q) {
        float4 qp = g_qpt[qbase + q];
        ax[q] = -2.0f*qp.x; ay[q] = -2.0f*qp.y; az[q] = -2.0f*qp.z;
        qw[q] = qp.w;
        lmin[q] = CUDART_INF_F;
        seed[q] = (int)(g_qkey[qbase + q] >> 16);
    }

    // Phase B: scan each DISTINCT seed cluster, updating all 8 lmins
    #pragma unroll
    for (int q = 0; q < GQ; ++q) {
        bool dup = false;
        #pragma unroll
        for (int j = 0; j < GQ; ++j) if (j < q) dup |= (seed[j] == seed[q]);
        if (!dup) {
            int2 sc = shcs[seed[q]];
            for (int o = lane; o < sc.y; o += 32) {
                float4 p = pts[sc.x + o];
                #pragma unroll
                for (int r = 0; r < GQ; ++r) {
                    float t = fmaf(ax[r], p.x, p.w);
                    t = fmaf(ay[r], p.y, t);
                    t = fmaf(az[r], p.z, t);
                    lmin[r] = fminf(lmin[r], t);
                }
            }
        }
    }
    float best[GQ];
    #pragma unroll
    for (int q = 0; q < GQ; ++q)
        best[q] = sqrtf(fmaxf(warpMin(lmin[q]) + qw[q], 0.0f));

    // Phase C1: union candidate list over the 8 queries
    int nc = 0;
    #pragma unroll
    for (int k = 0; k < 32; ++k) {
        const int cid = k*32 + lane;
        float4 c = shc[cid];
        float r = shr[cid];
        bool pred = false;
        #pragma unroll
        for (int q = 0; q < GQ; ++q) {
            float t = fmaf(ax[q], c.x, c.w);
            t = fmaf(ay[q], c.y, t);
            t = fmaf(az[q], c.z, t);
            float thr = best[q] + r;
            pred |= (t + qw[q] < thr*thr);   // empty: c.w=+inf -> never
        }
        pred &= (cid != seed[0]);
        unsigned m = __ballot_sync(0xffffffffu, pred);
        if (pred) {
            int off = __popc(m & ((1u << lane) - 1u));
            mylist[nc + off] = (unsigned short)cid;
        }
        nc += __popc(m);
    }
    __syncwarp();

    // Phase C2: scan union list once; 2 clusters in flight; 8 queries per point
    int ci = 0;
    for (; ci + 2 <= nc; ci += 2) {
        int2 s0 = shcs[mylist[ci+0]];
        int2 s1 = shcs[mylist[ci+1]];
        int mx = max(s0.y, s1.y);
        for (int o = lane; o < mx; o += 32) {
            if (o < s0.y) {
                float4 p = pts[s0.x + o];
                #pragma unroll
                for (int q = 0; q < GQ; ++q) {
                    float t = fmaf(ax[q], p.x, p.w);
                    t = fmaf(ay[q], p.y, t);
                    t = fmaf(az[q], p.z, t);
                    lmin[q] = fminf(lmin[q], t);
                }
            }
            if (o < s1.y) {
                float4 p = pts[s1.x + o];
                #pragma unroll
                for (int q = 0; q < GQ; ++q) {
                    float t = fmaf(ax[q], p.x, p.w);
                    t = fmaf(ay[q], p.y, t);
                    t = fmaf(az[q], p.z, t);
                    lmin[q] = fminf(lmin[q], t);
                }
            }
        }
    }
    if (ci < nc) {
        int2 s0 = shcs[mylist[ci]];
        for (int o = lane; o < s0.y; o += 32) {
            float4 p = pts[s0.x + o];
            #pragma unroll
            for (int q = 0; q < GQ; ++q) {
                float t = fmaf(ax[q], p.x, p.w);
                t = fmaf(ay[q], p.y, t);
                t = fmaf(az[q], p.z, t);
                lmin[q] = fminf(lmin[q], t);
            }
        }
    }

    #pragma unroll
    for (int q = 0; q < GQ; ++q) {
        float best2 = warpMin(lmin[q]) + qw[q];
        if (lane == 0) {
            int qloc = (int)(g_qkey[qbase + q] & 0xFFFFu);
            g_mind[b*MM + qloc] = fmaxf(best2, 0.0f);
        }
    }
}

// Epilogue: warp-per-center max over S; last block writes the final scalar ----
__global__ void k_c2p(float* __restrict__ out) {
    const int lane = threadIdx.x & 31;
    const int wid  = (blockIdx.x * blockDim.x + threadIdx.x) >> 5;
    float v = sqrtf(fmaxf(g_mind[wid*SS + lane], 1e-12f));
    #pragma unroll
    for (int o = 16; o > 0; o >>= 1)
        v = fmaxf(v, __shfl_xor_sync(0xffffffffu, v, o));
    if (lane == 0) atomicAdd(&g_acc[2 + wid/NCC], v);

    __syncthreads();
    __threadfence();
    __shared__ int rank;
    if (threadIdx.x == 0) rank = atomicAdd(&g_done, 1);
    __syncthreads();
    if (threadIdx.x == 0 && rank == (int)gridDim.x - 1) {
        __threadfence();
        float r = 0.0f;
        #pragma unroll
        for (int b = 0; b < BB; ++b)
            r += g_acc[b] * (1.0f/NN) + g_acc[2 + b] * (1.0f/NCC);
        out[0] = r * (1.0f/BB);
    }
}

// ---------------------------------------------------------------------------
extern "C" void kernel_launch(void* const* d_in, const int* in_sizes, int n_in,
                              void* d_out, int out_size) {
    const float* centers = (const float*)d_in[0];
    const float* radius  = (const float*)d_in[1];
    const float* xyz     = (const float*)d_in[2];
    const float* sp      = (const float*)d_in[3];
    float* out = (float*)d_out;

    k_prep<<<(BB*NCC)/256, 256>>>(centers);
    k_p2c<<<dim3(NN/(256*P2C_PT), BB), 256>>>(xyz, radius);
    k_qprep<<<dim3(MM/(256*QP_PT), BB), 256>>>(sp);
    k_scan<<<1, 1024>>>();
    k_scatter<<<(BB*NN)/256, 256>>>(sp);
    k_nn<<<(BB*MM)/QPB, 32*NN_WARPS>>>();
    k_c2p<<<(BB*NCC)/8, 256>>>(out);
}

// round 14
// speedup vs baseline: 1.1566x; 1.1566x over previous
#include <cuda_runtime.h>
#include <math_constants.h>

#define BB   2
#define NN   32768
#define NCC  1024
#define SS   32
#define MM   (NCC*SS)          // 32768

#define NN_WARPS  8
#define GQ        8                 // queries per warp (grouped)
#define QPB       (NN_WARPS*GQ)    // 64 queries per block

// Scratch (no allocations allowed) ------------------------------------------
__device__ float4       g_xyzp [BB*NN];
__device__ float4       g_ctr  [BB*NCC];
__device__ float        g_csx [BB*NCC], g_csy[BB*NCC], g_csz[BB*NCC];
__device__ float4       g_cen [BB*NCC];   // member centroid (x,y,z,|cen|^2)
__device__ int          g_assign[BB*NN];
__device__ int          g_cnt [BB*NCC];
__device__ int          g_start[BB*NCC];
__device__ int          g_cur [BB*NCC];
__device__ unsigned int g_rmax2[BB*NCC];  // max member->centroid distance (bits)
__device__ float4       g_psort[BB*NN];
__device__ int          g_qseed[BB*MM];
__device__ int          g_qcnt [BB*NCC];
__device__ int          g_qcur [BB*NCC];
__device__ unsigned     g_qkey [BB*MM];   // (cid<<16) | q_local
__device__ float4       g_qpt  [BB*MM];
__device__ float        g_mind[BB*MM];
__device__ float        g_acc[4];
__device__ int          g_done;

// ---------------------------------------------------------------------------
__device__ __forceinline__ float warpMin(float v) {
    #pragma unroll
    for (int o = 16; o > 0; o >>= 1)
        v = fminf(v, __shfl_xor_sync(0xffffffffu, v, o));
    return v;
}

__inline__ __device__ float blockReduceSum(float v) {
    __shared__ float sw[32];
    #pragma unroll
    for (int o = 16; o > 0; o >>= 1) v += __shfl_down_sync(0xffffffffu, v, o);
    int lane = threadIdx.x & 31, w = threadIdx.x >> 5;
    if (lane == 0) sw[w] = v;
    __syncthreads();
    int nw = blockDim.x >> 5;
    v = (threadIdx.x < nw) ? sw[threadIdx.x] : 0.0f;
    if (w == 0) {
        #pragma unroll
        for (int o = 16; o > 0; o >>= 1) v += __shfl_down_sync(0xffffffffu, v, o);
    }
    return v;
}

// Init: pack centers, zero counters ------------------------------------------
__global__ void k_prep(const float* __restrict__ ctr) {
    int i = blockIdx.x * blockDim.x + threadIdx.x;   // 0..BB*NCC-1
    float x = ctr[3*i+0], y = ctr[3*i+1], z = ctr[3*i+2];
    g_ctr[i] = make_float4(x, y, z, x*x + y*y + z*z);
    g_cnt[i] = 0;
    g_qcnt[i] = 0;
    g_rmax2[i] = 0u;
    g_csx[i] = 0.f; g_csy[i] = 0.f; g_csz[i] = 0.f;
    if (i < 4) g_acc[i] = 0.0f;
    if (i == 4) g_done = 0;
}

// Part 1: xyz -> nearest center (packs xyz, accumulates member sums) ----------
__global__ void k_p2c(const float* __restrict__ xyz, const float* __restrict__ radius) {
    __shared__ float4 shc[NCC];
    const int b = blockIdx.y;
    const int n = blockIdx.x * blockDim.x + threadIdx.x;
    for (int i = threadIdx.x; i < NCC; i += blockDim.x)
        shc[i] = g_ctr[b*NCC + i];
    __syncthreads();

    const float* pp = xyz + ((long long)b*NN + n) * 3;
    float x = pp[0], y = pp[1], z = pp[2];
    float qw = x*x + y*y + z*z;
    g_xyzp[b*NN + n] = make_float4(x, y, z, qw);
    float ax = -2.0f*x, ay = -2.0f*y, az = -2.0f*z;
    float tmin = CUDART_INF_F;
    int idx = 0;
    #pragma unroll 4
    for (int c = 0; c < NCC; ++c) {
        float4 p = shc[c];
        float t = fmaf(ax, p.x, p.w);
        t = fmaf(ay, p.y, t);
        t = fmaf(az, p.z, t);
        if (t < tmin) { tmin = t; idx = c; }   // strict < == jnp.argmin
    }
    float cd = sqrtf(fmaxf(tmin + qw, 1e-12f));
    float contrib = fmaxf(cd - radius[b*NCC + idx], 0.0f);
    float s = blockReduceSum(contrib);
    if (threadIdx.x == 0) atomicAdd(&g_acc[b], s);

    int bc = b*NCC + idx;
    g_assign[b*NN + n] = idx;
    atomicAdd(&g_cnt[bc], 1);
    atomicAdd(&g_csx[bc], x);
    atomicAdd(&g_csy[bc], y);
    atomicAdd(&g_csz[bc], z);
}

// Query prepass: seed = nearest non-empty center -------------------------------
__global__ void k_qprep(const float* __restrict__ sp) {
    __shared__ float4 shc[NCC];
    const int b = blockIdx.y;
    const int m = blockIdx.x * blockDim.x + threadIdx.x;
    for (int i = threadIdx.x; i < NCC; i += blockDim.x) {
        float4 c = g_ctr[b*NCC + i];
        if (g_cnt[b*NCC + i] == 0) c.w = CUDART_INF_F;
        shc[i] = c;
    }
    __syncthreads();

    const float* p = sp + ((long long)b*MM + m) * 3;
    float x = p[0], y = p[1], z = p[2];
    float ax = -2.0f*x, ay = -2.0f*y, az = -2.0f*z;
    float tmin = CUDART_INF_F;
    int idx = 0;
    #pragma unroll 4
    for (int c = 0; c < NCC; ++c) {
        float4 cc = shc[c];
        float t = fmaf(ax, cc.x, cc.w);
        t = fmaf(ay, cc.y, t);
        t = fmaf(az, cc.z, t);
        if (t < tmin) { tmin = t; idx = c; }
    }
    g_qseed[b*MM + m] = idx;
    atomicAdd(&g_qcnt[b*NCC + idx], 1);
}

// Warp-shuffle prefix scans + centroid computation ------------------------------
__device__ __forceinline__ void scanHalf(const int* __restrict__ cnt,
                                         int* out0, int* out1, bool dual,
                                         int* wsum) {
    const int t = threadIdx.x, lane = t & 31, w = t >> 5;
    int c0 = cnt[2*t], c1 = cnt[2*t+1];
    int v = c0 + c1, s = v;
    #pragma unroll
    for (int o = 1; o < 32; o <<= 1) {
        int n = __shfl_up_sync(0xffffffffu, s, o);
        if (lane >= o) s += n;
    }
    if (lane == 31) wsum[w] = s;
    __syncthreads();
    if (w == 0) {
        int x = wsum[lane];
        #pragma unroll
        for (int o = 1; o < 32; o <<= 1) {
            int n = __shfl_up_sync(0xffffffffu, x, o);
            if (lane >= o) x += n;
        }
        wsum[lane] = x;
    }
    __syncthreads();
    int base = (w > 0) ? wsum[w-1] : 0;
    int excl = base + s - v;
    out0[2*t]   = excl;  out0[2*t+1] = excl + c0;
    if (dual) { out1[2*t] = excl; out1[2*t+1] = excl + c0; }
    __syncthreads();
}

__global__ void k_scan() {
    __shared__ int wsum[32];
    scanHalf(g_cnt,  g_start, g_cur, true,  wsum);
    scanHalf(g_qcnt, g_qcur,  0,     false, wsum);
    const int t = threadIdx.x;
    #pragma unroll
    for (int j = 0; j < 2; ++j) {
        int i = 2*t + j;
        int c = g_cnt[i];
        float inv = (c > 0) ? 1.0f/(float)c : 0.0f;
        float cx = g_csx[i]*inv, cy = g_csy[i]*inv, cz = g_csz[i]*inv;
        g_cen[i] = make_float4(cx, cy, cz, cx*cx + cy*cy + cz*cz);
    }
}

// Merged scatter + centroid covering radius ------------------------------------
__global__ void k_scatter(const float* __restrict__ sp) {
    int i = blockIdx.x * blockDim.x + threadIdx.x;   // 0..BB*NN-1 (== BB*MM-1)
    if (i >= BB*NN) return;
    int b = i / NN;
    int bc = b*NCC + g_assign[i];
    int pos = atomicAdd(&g_cur[bc], 1);
    float4 pt = g_xyzp[i];
    g_psort[pos] = pt;
    float4 cen = g_cen[bc];
    float dx = pt.x - cen.x, dy = pt.y - cen.y, dz = pt.z - cen.z;
    float rd = sqrtf(dx*dx + dy*dy + dz*dz);
    atomicMax(&g_rmax2[bc], __float_as_uint(rd));    // rd >= 0

    int m = i - b*MM;                                 // NN == MM
    int cid = g_qseed[i];
    int qpos = atomicAdd(&g_qcur[b*NCC + cid], 1);
    const float* p = sp + (long long)i * 3;
    float x = p[0], y = p[1], z = p[2];
    g_qkey[qpos] = ((unsigned)cid << 16) | (unsigned)m;
    g_qpt[qpos]  = make_float4(x, y, z, x*x + y*y + z*z);
}

// Distance kernel body for one loaded point against all GQ queries -------------
#define UPDATE8(P)                                          \
    do {                                                    \
        _Pragma("unroll")                                   \
        for (int q = 0; q < GQ; ++q) {                      \
            float t = fmaf(ax[q], (P).x, (P).w);            \
            t = fmaf(ay[q], (P).y, t);                      \
            t = fmaf(az[q], (P).z, t);                      \
            lmin[q] = fminf(lmin[q], t);                    \
        }                                                   \
    } while (0)

// Part 2: exact NN, 8 sorted queries per warp; centroid-anchored pruning -------
__global__ void __launch_bounds__(32*NN_WARPS)
k_nn() {
    __shared__ float4 shc[NCC];    // member centroids; w=+inf if empty
    __shared__ int2   shcs[NCC];   // (start, count)
    __shared__ float  shr[NCC];    // padded centroid covering radius
    __shared__ unsigned short shlist[NN_WARPS][NCC];
    const int tid  = threadIdx.x;
    const int lane = tid & 31;
    const int warp = tid >> 5;
    const int qbase = blockIdx.x * QPB + warp * GQ;
    const int b = (blockIdx.x * QPB) / MM;

    for (int i = tid; i < NCC; i += 32*NN_WARPS) {
        int cnt = g_cnt[b*NCC + i];
        float4 c = g_cen[b*NCC + i];
        if (cnt == 0) c.w = CUDART_INF_F;
        shc[i]  = c;
        shcs[i] = make_int2(g_start[b*NCC + i], cnt);
        shr[i]  = __uint_as_float(g_rmax2[b*NCC + i]) * 1.000002f + 1e-6f;
    }
    __syncthreads();

    const float4* __restrict__ pts = g_psort;
    unsigned short* const mylist = shlist[warp];

    float ax[GQ], ay[GQ], az[GQ], qw[GQ], lmin[GQ];
    int   seed[GQ];
    #pragma unroll
    for (int q = 0; q < GQ; ++q) {
        float4 qp = g_qpt[qbase + q];
        ax[q] = -2.0f*qp.x; ay[q] = -2.0f*qp.y; az[q] = -2.0f*qp.z;
        qw[q] = qp.w;
        lmin[q] = CUDART_INF_F;
        seed[q] = (int)(g_qkey[qbase + q] >> 16);
    }

    // Phase B: scan each DISTINCT seed cluster, updating all 8 lmins
    #pragma unroll
    for (int q = 0; q < GQ; ++q) {
        bool dup = false;
        #pragma unroll
        for (int j = 0; j < GQ; ++j) if (j < q) dup |= (seed[j] == seed[q]);
        if (!dup) {
            int2 sc = shcs[seed[q]];
            for (int o = lane; o < sc.y; o += 32) {
                float4 p = pts[sc.x + o];
                UPDATE8(p);
            }
        }
    }
    float best[GQ];
    #pragma unroll
    for (int q = 0; q < GQ; ++q)
        best[q] = sqrtf(fmaxf(warpMin(lmin[q]) + qw[q], 0.0f));

    // Phase C1: union candidate list over the 8 queries
    int nc = 0;
    #pragma unroll
    for (int k = 0; k < 32; ++k) {
        const int cid = k*32 + lane;
        float4 c = shc[cid];
        float r = shr[cid];
        bool pred = false;
        #pragma unroll
        for (int q = 0; q < GQ; ++q) {
            float t = fmaf(ax[q], c.x, c.w);
            t = fmaf(ay[q], c.y, t);
            t = fmaf(az[q], c.z, t);
            float thr = best[q] + r;
            pred |= (t + qw[q] < thr*thr);   // empty: c.w=+inf -> never
        }
        pred &= (cid != seed[0]);
        unsigned m = __ballot_sync(0xffffffffu, pred);
        if (pred) {
            int off = __popc(m & ((1u << lane) - 1u));
            mylist[nc + off] = (unsigned short)cid;
        }
        nc += __popc(m);
    }
    __syncwarp();

    // Phase C2: scan union list; 4 clusters in flight (MLP=4); 8 queries/point
    int ci = 0;
    for (; ci + 4 <= nc; ci += 4) {
        int2 s0 = shcs[mylist[ci+0]];
        int2 s1 = shcs[mylist[ci+1]];
        int2 s2 = shcs[mylist[ci+2]];
        int2 s3 = shcs[mylist[ci+3]];
        int mx = max(max(s0.y, s1.y), max(s2.y, s3.y));
        for (int o = lane; o < mx; o += 32) {
            if (o < s0.y) { float4 p = pts[s0.x + o]; UPDATE8(p); }
            if (o < s1.y) { float4 p = pts[s1.x + o]; UPDATE8(p); }
            if (o < s2.y) { float4 p = pts[s2.x + o]; UPDATE8(p); }
            if (o < s3.y) { float4 p = pts[s3.x + o]; UPDATE8(p); }
        }
    }
    for (; ci < nc; ++ci) {
        int2 s0 = shcs[mylist[ci]];
        for (int o = lane; o < s0.y; o += 32) {
            float4 p = pts[s0.x + o];
            UPDATE8(p);
        }
    }

    #pragma unroll
    for (int q = 0; q < GQ; ++q) {
        float best2 = warpMin(lmin[q]) + qw[q];
        if (lane == 0) {
            int qloc = (int)(g_qkey[qbase + q] & 0xFFFFu);
            g_mind[b*MM + qloc] = fmaxf(best2, 0.0f);
        }
    }
}

// Epilogue: warp-per-center max over S; last block writes the final scalar ----
__global__ void k_c2p(float* __restrict__ out) {
    const int lane = threadIdx.x & 31;
    const int wid  = (blockIdx.x * blockDim.x + threadIdx.x) >> 5;
    float v = sqrtf(fmaxf(g_mind[wid*SS + lane], 1e-12f));
    #pragma unroll
    for (int o = 16; o > 0; o >>= 1)
        v = fmaxf(v, __shfl_xor_sync(0xffffffffu, v, o));
    if (lane == 0) atomicAdd(&g_acc[2 + wid/NCC], v);

    __syncthreads();
    __threadfence();
    __shared__ int rank;
    if (threadIdx.x == 0) rank = atomicAdd(&g_done, 1);
    __syncthreads();
    if (threadIdx.x == 0 && rank == (int)gridDim.x - 1) {
        __threadfence();
        float r = 0.0f;
        #pragma unroll
        for (int b = 0; b < BB; ++b)
            r += g_acc[b] * (1.0f/NN) + g_acc[2 + b] * (1.0f/NCC);
        out[0] = r * (1.0f/BB);
    }
}

// ---------------------------------------------------------------------------
extern "C" void kernel_launch(void* const* d_in, const int* in_sizes, int n_in,
                              void* d_out, int out_size) {
    const float* centers = (const float*)d_in[0];
    const float* radius  = (const float*)d_in[1];
    const float* xyz     = (const float*)d_in[2];
    const float* sp      = (const float*)d_in[3];
    float* out = (float*)d_out;

    k_prep<<<(BB*NCC)/256, 256>>>(centers);
    k_p2c<<<dim3(NN/256, BB), 256>>>(xyz, radius);
    k_qprep<<<dim3(MM/256, BB), 256>>>(sp);
    k_scan<<<1, 1024>>>();
    k_scatter<<<(BB*NN)/256, 256>>>(sp);
    k_nn<<<(BB*MM)/QPB, 32*NN_WARPS>>>();
    k_c2p<<<(BB*NCC)/8, 256>>>(out);
}

// round 15
// speedup vs baseline: 1.1569x; 1.0002x over previous
#include <cuda_runtime.h>
#include <math_constants.h>

#define BB   2
#define NN   32768
#define NCC  1024
#define SS   32
#define MM   (NCC*SS)          // 32768

#define NN_WARPS  8
#define GQ        8                 // queries per warp (grouped)
#define QPB       (NN_WARPS*GQ)    // 64 queries per block

#define TAIL_BLOCKS 512             // k_p2c (256) + k_qprep (256)

// Scratch (no allocations allowed) ------------------------------------------
__device__ float4       g_xyzp [BB*NN];
__device__ float4       g_ctr  [BB*NCC];
__device__ float        g_csx [BB*NCC], g_csy[BB*NCC], g_csz[BB*NCC];
__device__ float4       g_cen [BB*NCC];   // member centroid (x,y,z,|cen|^2)
__device__ int          g_assign[BB*NN];
__device__ int          g_cnt [BB*NCC];
__device__ int          g_start[BB*NCC];
__device__ int          g_cur [BB*NCC];
__device__ unsigned int g_rmax2[BB*NCC];  // max member->centroid distance (bits)
__device__ float4       g_psort[BB*NN];
__device__ int          g_qseed[BB*MM];
__device__ int          g_qcnt [BB*NCC];
__device__ int          g_qcur [BB*NCC];
__device__ unsigned     g_qkey [BB*MM];   // (cid<<16) | q_local
__device__ float4       g_qpt  [BB*MM];
__device__ float        g_mind[BB*MM];
__device__ float        g_acc[4];
__device__ int          g_done;            // c2p final-block counter
__device__ int          g_done2;           // p2c+qprep tail counter

// ---------------------------------------------------------------------------
__device__ __forceinline__ float warpMin(float v) {
    #pragma unroll
    for (int o = 16; o > 0; o >>= 1)
        v = fminf(v, __shfl_xor_sync(0xffffffffu, v, o));
    return v;
}

__inline__ __device__ float blockReduceSum(float v) {
    __shared__ float sw[32];
    #pragma unroll
    for (int o = 16; o > 0; o >>= 1) v += __shfl_down_sync(0xffffffffu, v, o);
    int lane = threadIdx.x & 31, w = threadIdx.x >> 5;
    if (lane == 0) sw[w] = v;
    __syncthreads();
    int nw = blockDim.x >> 5;
    v = (threadIdx.x < nw) ? sw[threadIdx.x] : 0.0f;
    if (w == 0) {
        #pragma unroll
        for (int o = 16; o > 0; o >>= 1) v += __shfl_down_sync(0xffffffffu, v, o);
    }
    return v;
}

// 256-thread block scan over 2048 counts -> exclusive prefixes ------------------
__device__ __forceinline__ void scan2048_block(const int* __restrict__ cnt,
                                               int* __restrict__ out0,
                                               int* __restrict__ out1, bool dual) {
    __shared__ int ws[8];
    const int t = threadIdx.x, lane = t & 31, w = t >> 5;
    int v[8]; int tot = 0;
    #pragma unroll
    for (int j = 0; j < 8; ++j) { v[j] = cnt[t*8 + j]; tot += v[j]; }
    int s = tot;
    #pragma unroll
    for (int o = 1; o < 32; o <<= 1) {
        int n = __shfl_up_sync(0xffffffffu, s, o);
        if (lane >= o) s += n;
    }
    if (lane == 31) ws[w] = s;
    __syncthreads();
    int base = 0;
    #pragma unroll
    for (int j = 0; j < 8; ++j) if (j < w) base += ws[j];
    int excl = base + s - tot;
    #pragma unroll
    for (int j = 0; j < 8; ++j) {
        out0[t*8 + j] = excl;
        if (dual) out1[t*8 + j] = excl;
        excl += v[j];
    }
    __syncthreads();
}

// Tail: run by the LAST of the 512 p2c/qprep blocks --------------------------
__device__ __forceinline__ void pipelineTail() {
    __threadfence();
    __shared__ int srank;
    if (threadIdx.x == 0) srank = atomicAdd(&g_done2, 1);
    __syncthreads();
    if (srank != TAIL_BLOCKS - 1) return;
    __threadfence();
    scan2048_block(g_cnt,  g_start, g_cur, true);
    scan2048_block(g_qcnt, g_qcur,  0,     false);
    const int t = threadIdx.x;
    #pragma unroll
    for (int j = 0; j < 8; ++j) {
        int i = t*8 + j;
        int c = g_cnt[i];
        float inv = (c > 0) ? 1.0f/(float)c : 0.0f;
        float cx = g_csx[i]*inv, cy = g_csy[i]*inv, cz = g_csz[i]*inv;
        g_cen[i] = make_float4(cx, cy, cz, cx*cx + cy*cy + cz*cz);
    }
}

// Init: pack centers, zero counters ------------------------------------------
__global__ void k_prep(const float* __restrict__ ctr) {
    int i = blockIdx.x * blockDim.x + threadIdx.x;   // 0..BB*NCC-1
    float x = ctr[3*i+0], y = ctr[3*i+1], z = ctr[3*i+2];
    g_ctr[i] = make_float4(x, y, z, x*x + y*y + z*z);
    g_cnt[i] = 0;
    g_qcnt[i] = 0;
    g_rmax2[i] = 0u;
    g_csx[i] = 0.f; g_csy[i] = 0.f; g_csz[i] = 0.f;
    if (i < 4) g_acc[i] = 0.0f;
    if (i == 4) g_done = 0;
    if (i == 5) g_done2 = 0;
}

// Part 1: xyz -> nearest center (packs xyz, accumulates member sums) ----------
__global__ void k_p2c(const float* __restrict__ xyz, const float* __restrict__ radius) {
    __shared__ float4 shc[NCC];
    const int b = blockIdx.y;
    const int n = blockIdx.x * blockDim.x + threadIdx.x;
    for (int i = threadIdx.x; i < NCC; i += blockDim.x)
        shc[i] = g_ctr[b*NCC + i];
    __syncthreads();

    const float* pp = xyz + ((long long)b*NN + n) * 3;
    float x = pp[0], y = pp[1], z = pp[2];
    float qw = x*x + y*y + z*z;
    g_xyzp[b*NN + n] = make_float4(x, y, z, qw);
    float ax = -2.0f*x, ay = -2.0f*y, az = -2.0f*z;
    float tmin = CUDART_INF_F;
    int idx = 0;
    #pragma unroll 4
    for (int c = 0; c < NCC; ++c) {
        float4 p = shc[c];
        float t = fmaf(ax, p.x, p.w);
        t = fmaf(ay, p.y, t);
        t = fmaf(az, p.z, t);
        if (t < tmin) { tmin = t; idx = c; }   // strict < == jnp.argmin
    }
    float cd = sqrtf(fmaxf(tmin + qw, 1e-12f));
    float contrib = fmaxf(cd - radius[b*NCC + idx], 0.0f);
    float s = blockReduceSum(contrib);
    if (threadIdx.x == 0) atomicAdd(&g_acc[b], s);

    int bc = b*NCC + idx;
    g_assign[b*NN + n] = idx;
    atomicAdd(&g_cnt[bc], 1);
    atomicAdd(&g_csx[bc], x);
    atomicAdd(&g_csy[bc], y);
    atomicAdd(&g_csz[bc], z);

    pipelineTail();
}

// Query prepass: seed = nearest center (no count dependency) -------------------
__global__ void k_qprep(const float* __restrict__ sp) {
    __shared__ float4 shc[NCC];
    const int b = blockIdx.y;
    const int m = blockIdx.x * blockDim.x + threadIdx.x;
    for (int i = threadIdx.x; i < NCC; i += blockDim.x)
        shc[i] = g_ctr[b*NCC + i];
    __syncthreads();

    const float* p = sp + ((long long)b*MM + m) * 3;
    float x = p[0], y = p[1], z = p[2];
    float ax = -2.0f*x, ay = -2.0f*y, az = -2.0f*z;
    float tmin = CUDART_INF_F;
    int idx = 0;
    #pragma unroll 4
    for (int c = 0; c < NCC; ++c) {
        float4 cc = shc[c];
        float t = fmaf(ax, cc.x, cc.w);
        t = fmaf(ay, cc.y, t);
        t = fmaf(az, cc.z, t);
        if (t < tmin) { tmin = t; idx = c; }
    }
    g_qseed[b*MM + m] = idx;
    atomicAdd(&g_qcnt[b*NCC + idx], 1);

    pipelineTail();
}

// Merged scatter + centroid covering radius ------------------------------------
__global__ void k_scatter(const float* __restrict__ sp) {
    int i = blockIdx.x * blockDim.x + threadIdx.x;   // 0..BB*NN-1 (== BB*MM-1)
    if (i >= BB*NN) return;
    int b = i / NN;
    int bc = b*NCC + g_assign[i];
    int pos = atomicAdd(&g_cur[bc], 1);
    float4 pt = g_xyzp[i];
    g_psort[pos] = pt;
    float4 cen = g_cen[bc];
    float dx = pt.x - cen.x, dy = pt.y - cen.y, dz = pt.z - cen.z;
    float rd = sqrtf(dx*dx + dy*dy + dz*dz);
    atomicMax(&g_rmax2[bc], __float_as_uint(rd));    // rd >= 0

    int m = i - b*MM;                                 // NN == MM
    int cid = g_qseed[i];
    int qpos = atomicAdd(&g_qcur[b*NCC + cid], 1);
    const float* p = sp + (long long)i * 3;
    float x = p[0], y = p[1], z = p[2];
    g_qkey[qpos] = ((unsigned)cid << 16) | (unsigned)m;
    g_qpt[qpos]  = make_float4(x, y, z, x*x + y*y + z*z);
}

// Distance update for one loaded point against all GQ queries -------------------
#define UPDATE8(P)                                          \
    do {                                                    \
        _Pragma("unroll")                                   \
        for (int q = 0; q < GQ; ++q) {                      \
            float t = fmaf(ax[q], (P).x, (P).w);            \
            t = fmaf(ay[q], (P).y, t);                      \
            t = fmaf(az[q], (P).z, t);                      \
            lmin[q] = fminf(lmin[q], t);                    \
        }                                                   \
    } while (0)

// Part 2: exact NN, 8 sorted queries per warp; centroid-anchored pruning -------
__global__ void __launch_bounds__(32*NN_WARPS)
k_nn() {
    __shared__ float4 shc[NCC];    // member centroids; w=+inf if empty
    __shared__ int2   shcs[NCC];   // (start, count)
    __shared__ float  shr[NCC];    // padded centroid covering radius
    __shared__ unsigned short shlist[NN_WARPS][NCC];
    const int tid  = threadIdx.x;
    const int lane = tid & 31;
    const int warp = tid >> 5;
    const int qbase = blockIdx.x * QPB + warp * GQ;
    const int b = (blockIdx.x * QPB) / MM;

    for (int i = tid; i < NCC; i += 32*NN_WARPS) {
        int cnt = g_cnt[b*NCC + i];
        float4 c = g_cen[b*NCC + i];
        if (cnt == 0) c.w = CUDART_INF_F;
        shc[i]  = c;
        shcs[i] = make_int2(g_start[b*NCC + i], cnt);
        shr[i]  = __uint_as_float(g_rmax2[b*NCC + i]) * 1.000002f + 1e-6f;
    }
    __syncthreads();

    const float4* __restrict__ pts = g_psort;
    unsigned short* const mylist = shlist[warp];

    float ax[GQ], ay[GQ], az[GQ], qw[GQ], lmin[GQ];
    int   seed[GQ];
    #pragma unroll
    for (int q = 0; q < GQ; ++q) {
        float4 qp = g_qpt[qbase + q];
        ax[q] = -2.0f*qp.x; ay[q] = -2.0f*qp.y; az[q] = -2.0f*qp.z;
        qw[q] = qp.w;
        lmin[q] = CUDART_INF_F;
        seed[q] = (int)(g_qkey[qbase + q] >> 16);
    }

    // Rare repair: if a seed cluster is empty, re-seed with nearest NON-EMPTY
    // centroid (shc.w=+inf for empties). Warp-uniform branch.
    #pragma unroll
    for (int q = 0; q < GQ; ++q) {
        if (shcs[seed[q]].y == 0) {
            unsigned pk = 0xFFFFFFFFu;
            #pragma unroll
            for (int k = 0; k < 32; ++k) {
                const int cid = k*32 + lane;
                float4 c = shc[cid];
                float t = fmaf(ax[q], c.x, c.w);
                t = fmaf(ay[q], c.y, t);
                t = fmaf(az[q], c.z, t);
                float d2 = fmaxf(t + qw[q], 0.0f);
                unsigned v = (__float_as_uint(d2) & 0xFFFFFC00u) | (unsigned)cid;
                pk = min(pk, v);
            }
            pk = __reduce_min_sync(0xffffffffu, pk);
            seed[q] = (int)(pk & 1023u);
        }
    }

    // Phase B: scan each DISTINCT seed cluster, updating all 8 lmins
    #pragma unroll
    for (int q = 0; q < GQ; ++q) {
        bool dup = false;
        #pragma unroll
        for (int j = 0; j < GQ; ++j) if (j < q) dup |= (seed[j] == seed[q]);
        if (!dup) {
            int2 sc = shcs[seed[q]];
            for (int o = lane; o < sc.y; o += 32) {
                float4 p = pts[sc.x + o];
                UPDATE8(p);
            }
        }
    }
    float best[GQ];
    #pragma unroll
    for (int q = 0; q < GQ; ++q)
        best[q] = sqrtf(fmaxf(warpMin(lmin[q]) + qw[q], 0.0f));

    // Phase C1: union candidate list over the 8 queries
    int nc = 0;
    #pragma unroll
    for (int k = 0; k < 32; ++k) {
        const int cid = k*32 + lane;
        float4 c = shc[cid];
        float r = shr[cid];
        bool pred = false;
        #pragma unroll
        for (int q = 0; q < GQ; ++q) {
            float t = fmaf(ax[q], c.x, c.w);
            t = fmaf(ay[q], c.y, t);
            t = fmaf(az[q], c.z, t);
            float thr = best[q] + r;
            pred |= (t + qw[q] < thr*thr);   // empty: c.w=+inf -> never
        }
        pred &= (cid != seed[0]);
        unsigned m = __ballot_sync(0xffffffffu, pred);
        if (pred) {
            int off = __popc(m & ((1u << lane) - 1u));
            mylist[nc + off] = (unsigned short)cid;
        }
        nc += __popc(m);
    }
    __syncwarp();

    // Phase C2: scan union list; 4 clusters in flight; 8 queries per point
    int ci = 0;
    for (; ci + 4 <= nc; ci += 4) {
        int2 s0 = shcs[mylist[ci+0]];
        int2 s1 = shcs[mylist[ci+1]];
        int2 s2 = shcs[mylist[ci+2]];
        int2 s3 = shcs[mylist[ci+3]];
        int mx = max(max(s0.y, s1.y), max(s2.y, s3.y));
        for (int o = lane; o < mx; o += 32) {
            if (o < s0.y) { float4 p = pts[s0.x + o]; UPDATE8(p); }
            if (o < s1.y) { float4 p = pts[s1.x + o]; UPDATE8(p); }
            if (o < s2.y) { float4 p = pts[s2.x + o]; UPDATE8(p); }
            if (o < s3.y) { float4 p = pts[s3.x + o]; UPDATE8(p); }
        }
    }
    for (; ci < nc; ++ci) {
        int2 s0 = shcs[mylist[ci]];
        for (int o = lane; o < s0.y; o += 32) {
            float4 p = pts[s0.x + o];
            UPDATE8(p);
        }
    }

    #pragma unroll
    for (int q = 0; q < GQ; ++q) {
        float best2 = warpMin(lmin[q]) + qw[q];
        if (lane == 0) {
            int qloc = (int)(g_qkey[qbase + q] & 0xFFFFu);
            g_mind[b*MM + qloc] = fmaxf(best2, 0.0f);
        }
    }
}

// Epilogue: warp-per-center max over S; last block writes the final scalar ----
__global__ void k_c2p(float* __restrict__ out) {
    const int lane = threadIdx.x & 31;
    const int wid  = (blockIdx.x * blockDim.x + threadIdx.x) >> 5;
    float v = sqrtf(fmaxf(g_mind[wid*SS + lane], 1e-12f));
    #pragma unroll
    for (int o = 16; o > 0; o >>= 1)
        v = fmaxf(v, __shfl_xor_sync(0xffffffffu, v, o));
    if (lane == 0) atomicAdd(&g_acc[2 + wid/NCC], v);

    __syncthreads();
    __threadfence();
    __shared__ int rank;
    if (threadIdx.x == 0) rank = atomicAdd(&g_done, 1);
    __syncthreads();
    if (threadIdx.x == 0 && rank == (int)gridDim.x - 1) {
        __threadfence();
        float r = 0.0f;
        #pragma unroll
        for (int b = 0; b < BB; ++b)
            r += g_acc[b] * (1.0f/NN) + g_acc[2 + b] * (1.0f/NCC);
        out[0] = r * (1.0f/BB);
    }
}

// ---------------------------------------------------------------------------
extern "C" void kernel_launch(void* const* d_in, const int* in_sizes, int n_in,
                              void* d_out, int out_size) {
    const float* centers = (const float*)d_in[0];
    const float* radius  = (const float*)d_in[1];
    const float* xyz     = (const float*)d_in[2];
    const float* sp      = (const float*)d_in[3];
    float* out = (float*)d_out;

    // Fork/join streams for p2c || qprep (created per call; host-side only).
    cudaStream_t s2 = 0;
    cudaEvent_t evA = 0, evB = 0;
    bool forked = (cudaStreamCreateWithFlags(&s2, cudaStreamNonBlocking) == cudaSuccess)
               && (cudaEventCreateWithFlags(&evA, cudaEventDisableTiming) == cudaSuccess)
               && (cudaEventCreateWithFlags(&evB, cudaEventDisableTiming) == cudaSuccess);

    k_prep<<<(BB*NCC)/256, 256>>>(centers);

    if (forked) {
        cudaEventRecord(evA, 0);
        cudaStreamWaitEvent(s2, evA, 0);
        k_qprep<<<dim3(MM/256, BB), 256, 0, s2>>>(sp);
        k_p2c<<<dim3(NN/256, BB), 256>>>(xyz, radius);
        cudaEventRecord(evB, s2);
        cudaStreamWaitEvent(0, evB, 0);
    } else {
        k_p2c<<<dim3(NN/256, BB), 256>>>(xyz, radius);
        k_qprep<<<dim3(MM/256, BB), 256>>>(sp);
    }

    k_scatter<<<(BB*NN)/256, 256>>>(sp);
    k_nn<<<(BB*MM)/QPB, 32*NN_WARPS>>>();
    k_c2p<<<(BB*NCC)/8, 256>>>(out);
}